// round 2
// baseline (speedup 1.0000x reference)
#include <cuda_runtime.h>

#define N_NODES 50000
#define N_EDGES 800000
#define NODE_F  160     // 64 scalar + 32*3 vector
#define S_F     384     // s0:64  s1:192  s2:96  s3:32
#define TE      16      // edges per block in edge kernel

// Scratch (device globals — no allocations allowed)
__device__ float g_l[N_NODES * NODE_F];
__device__ float g_s[N_NODES * S_F];

// Packed fp32x2 FMA (2 FMAs per issue slot on sm_103a)
#define FMA_F32X2(acc, a, b) \
  asm volatile("fma.rn.f32x2 %0, %1, %2, %0;" : "+l"(acc) : "l"(a), "l"(b))

// Vector fp32 reduction (sm_90+): 4 adds in one L2 transaction
#define RED_ADD_V4(ptr, v0, v1, v2, v3)                                   \
  asm volatile("red.global.add.v4.f32 [%0], {%1,%2,%3,%4};"               \
               :: "l"(ptr), "f"(v0), "f"(v1), "f"(v2), "f"(v3) : "memory")

// ---------------------------------------------------------------------------
__global__ void zero_s_kernel() {
    const int n4 = N_NODES * S_F / 4;
    float4* p = reinterpret_cast<float4*>(g_s);
    float4 z = make_float4(0.f, 0.f, 0.f, 0.f);
    for (int i = blockIdx.x * blockDim.x + threadIdx.x; i < n4;
         i += gridDim.x * blockDim.x)
        p[i] = z;
}

// ---------------------------------------------------------------------------
// Node pre-pass: thread-per-node, weights in smem (broadcast LDS),
// accumulators in registers (indices only from fully-unrolled loops).
__global__ void __launch_bounds__(256)
node_pre_kernel(const float* __restrict__ x,
                const float* __restrict__ attr,
                const float* __restrict__ Wsi0,
                const float* __restrict__ Wsi1,
                const float* __restrict__ Wl10,
                const float* __restrict__ Wl11,
                float* __restrict__ out) {
    __shared__ float wS0[4096], wL0[4096], wS1[1024], wL1[1024];
    const int t = threadIdx.x;
    for (int i = t; i < 4096; i += 256) { wS0[i] = Wsi0[i]; wL0[i] = Wl10[i]; }
    for (int i = t; i < 1024; i += 256) { wS1[i] = Wsi1[i]; wL1[i] = Wl11[i]; }
    __syncthreads();

    const int n = blockIdx.x * 256 + t;
    if (n >= N_NODES) return;
    const float a  = attr[n];
    const float sA = a * 0.125f;                  // 1/sqrt(64)
    const float sV = a * 0.17677669529663689f;    // 1/sqrt(32)
    const float* xn = x   + (size_t)n * NODE_F;
    float* on       = out + (size_t)n * NODE_F;
    float* ln       = g_l + (size_t)n * NODE_F;

    // ---- scalar part (two passes: S then L, reusing acc registers) ----
#pragma unroll 1
    for (int pass = 0; pass < 2; pass++) {
        const float* W = pass ? wL0 : wS0;
        float* dst     = pass ? ln  : on;
        float acc[64];
#pragma unroll
        for (int i = 0; i < 64; i++) acc[i] = 0.f;
#pragma unroll 1
        for (int u4 = 0; u4 < 64; u4 += 4) {
            const float4 xv = *reinterpret_cast<const float4*>(xn + u4);
            const float xs[4] = {xv.x, xv.y, xv.z, xv.w};
#pragma unroll
            for (int j = 0; j < 4; j++) {
                const float* wrow = W + (u4 + j) * 64;
#pragma unroll
                for (int tt = 0; tt < 64; tt++) acc[tt] += xs[j] * wrow[tt];
            }
        }
#pragma unroll
        for (int t4 = 0; t4 < 64; t4 += 4)
            *reinterpret_cast<float4*>(dst + t4) =
                make_float4(acc[t4] * sA, acc[t4 + 1] * sA,
                            acc[t4 + 2] * sA, acc[t4 + 3] * sA);
    }

    // ---- vector part ----
#pragma unroll 1
    for (int pass = 0; pass < 2; pass++) {
        const float* W = pass ? wL1 : wS1;
        float* dst     = (pass ? ln : on) + 64;
        float acc[96];
#pragma unroll
        for (int i = 0; i < 96; i++) acc[i] = 0.f;
#pragma unroll 1
        for (int u4 = 0; u4 < 32; u4 += 4) {
            const float4 v0 = *reinterpret_cast<const float4*>(xn + 64 + u4 * 3);
            const float4 v1 = *reinterpret_cast<const float4*>(xn + 64 + u4 * 3 + 4);
            const float4 v2 = *reinterpret_cast<const float4*>(xn + 64 + u4 * 3 + 8);
            const float xs[12] = {v0.x, v0.y, v0.z, v0.w, v1.x, v1.y,
                                  v1.z, v1.w, v2.x, v2.y, v2.z, v2.w};
#pragma unroll
            for (int j = 0; j < 4; j++) {
                const float* wrow = W + (u4 + j) * 32;
#pragma unroll
                for (int w = 0; w < 32; w++) {
                    const float wg = wrow[w];
                    acc[w * 3 + 0] += xs[j * 3 + 0] * wg;
                    acc[w * 3 + 1] += xs[j * 3 + 1] * wg;
                    acc[w * 3 + 2] += xs[j * 3 + 2] * wg;
                }
            }
        }
#pragma unroll
        for (int i4 = 0; i4 < 96; i4 += 4)
            *reinterpret_cast<float4*>(dst + i4) =
                make_float4(acc[i4] * sV, acc[i4 + 1] * sV,
                            acc[i4 + 2] * sV, acc[i4 + 3] * sV);
    }
}

// ---------------------------------------------------------------------------
// Edge pass: radial MLP (FFMA2) + tensor-product messages + vector scatter.
__global__ void __launch_bounds__(192)
edge_kernel(const float* __restrict__ elemb,
            const float* __restrict__ eattr,
            const int*   __restrict__ esrc,
            const int*   __restrict__ edst,
            const float* __restrict__ Wfc1,
            const float* __restrict__ Wfc2) {
    __shared__ __align__(16) float sh_h[100][TE];
    __shared__ __align__(16) float sh_w[TE][192];
    __shared__ __align__(16) float sh_y[TE][NODE_F];
    __shared__ float sh_el[TE][10];
    __shared__ float sh_ea[TE][4];
    __shared__ int   sh_src[TE];
    __shared__ int   sh_dst[TE];

    const int t  = threadIdx.x;
    const int e0 = blockIdx.x * TE;

    if (t < TE) { sh_src[t] = esrc[e0 + t]; sh_dst[t] = edst[e0 + t]; }
    for (int i = t; i < TE * 10; i += 192)
        sh_el[i / 10][i % 10] = elemb[e0 * 10 + i];
    if (t >= 128 && t < 128 + TE * 4) {
        const int i = t - 128;
        sh_ea[i >> 2][i & 3] = eattr[e0 * 4 + i];
    }
    __syncthreads();

    // Stage y = g_l[src] (16 x 160 floats, float4)
    for (int i = t; i < TE * NODE_F / 4; i += 192) {
        const int e = i / 40, q = i % 40;
        reinterpret_cast<float4*>(sh_y[e])[q] =
            reinterpret_cast<const float4*>(g_l + (size_t)sh_src[e] * NODE_F)[q];
    }

    // Phase A: H = relu(elemb @ Wfc1 / sqrt(10)) * sqrt(2), layout [k][e]
    for (int idx = t; idx < 100 * TE; idx += 192) {
        const int e = idx & 15, k = idx >> 4;
        float acc = 0.f;
#pragma unroll
        for (int b = 0; b < 10; b++)
            acc += sh_el[e][b] * Wfc1[b * 100 + k];
        acc *= 0.31622776601683794f;
        sh_h[k][e] = fmaxf(acc, 0.f) * 1.4142135623730951f;
    }
    __syncthreads();

    // Phase B: w[e][t] = sum_k H[e][k] * Wfc2[k][t]  (packed f32x2 over edge pairs)
    unsigned long long acc2[8];
#pragma unroll
    for (int p = 0; p < 8; p++) acc2[p] = 0ull;
#pragma unroll 4
    for (int k = 0; k < 100; k++) {
        const float wf = Wfc2[k * 192 + t];
        unsigned long long wff;
        asm("mov.b64 %0, {%1, %1};" : "=l"(wff) : "r"(__float_as_uint(wf)));
        const ulonglong2* hp = reinterpret_cast<const ulonglong2*>(sh_h[k]);
        const ulonglong2 q0 = hp[0], q1 = hp[1], q2 = hp[2], q3 = hp[3];
        FMA_F32X2(acc2[0], q0.x, wff); FMA_F32X2(acc2[1], q0.y, wff);
        FMA_F32X2(acc2[2], q1.x, wff); FMA_F32X2(acc2[3], q1.y, wff);
        FMA_F32X2(acc2[4], q2.x, wff); FMA_F32X2(acc2[5], q2.y, wff);
        FMA_F32X2(acc2[6], q3.x, wff); FMA_F32X2(acc2[7], q3.y, wff);
    }
    const float SW = 0.025f;   // (1/sqrt(100)) * (1/sqrt(16))
#pragma unroll
    for (int p = 0; p < 8; p++) {
        float lo, hi;
        asm("mov.b64 {%0, %1}, %2;" : "=f"(lo), "=f"(hi) : "l"(acc2[p]));
        sh_w[2 * p][t]     = lo * SW;
        sh_w[2 * p + 1][t] = hi * SW;
    }
    __syncthreads();

    // Phase C: 12 threads per edge, each owns 32 contiguous features (8 x v4 RED).
    // Chunk boundaries (multiples of 32) align with region boundaries 64/256/352.
    const int e = t / 12;
    const int c = t % 12;
    const int d = sh_dst[e];
    float* gsd = g_s + (size_t)d * S_F;
    const float ea0 = sh_ea[e][0], ea1 = sh_ea[e][1],
                ea2 = sh_ea[e][2], ea3 = sh_ea[e][3];
    const float* we = sh_w[e];
    const float* ye = sh_y[e];

    if (c < 2) {                       // s0: f in [0,64)
        const int f0 = c * 32;
#pragma unroll
        for (int i = 0; i < 8; i++) {
            const int f = f0 + i * 4;
            RED_ADD_V4(gsd + f,
                       we[f + 0] * ye[f + 0] * ea0,
                       we[f + 1] * ye[f + 1] * ea0,
                       we[f + 2] * ye[f + 2] * ea0,
                       we[f + 3] * ye[f + 3] * ea0);
        }
    } else if (c < 8) {                // s1: idx in [0,192), layout u*3+d
        const int base = (c - 2) * 32;
#pragma unroll
        for (int i = 0; i < 8; i++) {
            const int idx = base + i * 4;
            float v[4];
#pragma unroll
            for (int j = 0; j < 4; j++) {
                const int id = idx + j;
                const int u = id / 3, dd = id - 3 * u;
                const float eav = (dd == 0) ? ea1 : ((dd == 1) ? ea2 : ea3);
                v[j] = we[64 + u] * ye[u] * eav;
            }
            RED_ADD_V4(gsd + 64 + idx, v[0], v[1], v[2], v[3]);
        }
    } else if (c < 11) {               // s2: idx in [0,96), layout u*3+d
        const int base = (c - 8) * 32;
#pragma unroll
        for (int i = 0; i < 8; i++) {
            const int idx = base + i * 4;
            float v[4];
#pragma unroll
            for (int j = 0; j < 4; j++) {
                const int id = idx + j;
                const int u = id / 3;
                v[j] = we[128 + u] * ea0 * ye[64 + id];
            }
            RED_ADD_V4(gsd + 256 + idx, v[0], v[1], v[2], v[3]);
        }
    } else {                           // s3: u in [0,32)
#pragma unroll
        for (int i = 0; i < 8; i++) {
            float v[4];
#pragma unroll
            for (int j = 0; j < 4; j++) {
                const int u = i * 4 + j;
                const float dot = ye[64 + 3 * u] * ea1 + ye[64 + 3 * u + 1] * ea2 +
                                  ye[64 + 3 * u + 2] * ea3;
                v[j] = we[160 + u] * dot * 0.5773502691896258f;  // 1/sqrt(3)
            }
            RED_ADD_V4(gsd + 352 + i * 4, v[0], v[1], v[2], v[3]);
        }
    }
}

// ---------------------------------------------------------------------------
// Node post-pass: thread-per-node, weights in smem, acc in registers.
__global__ void __launch_bounds__(256)
node_post_kernel(const float* __restrict__ attr,
                 const float* __restrict__ W00,
                 const float* __restrict__ W10,
                 const float* __restrict__ W01,
                 const float* __restrict__ W11,
                 float* __restrict__ out) {
    __shared__ float w00[4096], w10[2048], w01[2048], w11[1024];
    const int t = threadIdx.x;
    for (int i = t; i < 4096; i += 256) w00[i] = W00[i];
    for (int i = t; i < 2048; i += 256) { w10[i] = W10[i]; w01[i] = W01[i]; }
    for (int i = t; i < 1024; i += 256) w11[i] = W11[i];
    __syncthreads();

    const int n = blockIdx.x * 256 + t;
    if (n >= N_NODES) return;
    const float sc = attr[n] * 0.05103103630798288f;  // 0.5 / sqrt(96)
    const float* sn = g_s + (size_t)n * S_F;
    float* on       = out + (size_t)n * NODE_F;

    // ---- o0: s0 @ W00 + s3 @ W10 ----
    {
        float acc[64];
#pragma unroll
        for (int i = 0; i < 64; i++) acc[i] = 0.f;
#pragma unroll 1
        for (int u4 = 0; u4 < 64; u4 += 4) {
            const float4 sv = *reinterpret_cast<const float4*>(sn + u4);
            const float xs[4] = {sv.x, sv.y, sv.z, sv.w};
#pragma unroll
            for (int j = 0; j < 4; j++) {
                const float* wrow = w00 + (u4 + j) * 64;
#pragma unroll
                for (int tt = 0; tt < 64; tt++) acc[tt] += xs[j] * wrow[tt];
            }
        }
#pragma unroll 1
        for (int u4 = 0; u4 < 32; u4 += 4) {
            const float4 sv = *reinterpret_cast<const float4*>(sn + 352 + u4);
            const float xs[4] = {sv.x, sv.y, sv.z, sv.w};
#pragma unroll
            for (int j = 0; j < 4; j++) {
                const float* wrow = w10 + (u4 + j) * 64;
#pragma unroll
                for (int tt = 0; tt < 64; tt++) acc[tt] += xs[j] * wrow[tt];
            }
        }
#pragma unroll
        for (int t4 = 0; t4 < 64; t4 += 4) {
            float4 o = *reinterpret_cast<const float4*>(on + t4);
            o.x += acc[t4] * sc;     o.y += acc[t4 + 1] * sc;
            o.z += acc[t4 + 2] * sc; o.w += acc[t4 + 3] * sc;
            *reinterpret_cast<float4*>(on + t4) = o;
        }
    }

    // ---- o1: s1 @ W01 + s2 @ W11 ----
    {
        float acc[96];
#pragma unroll
        for (int i = 0; i < 96; i++) acc[i] = 0.f;
#pragma unroll 1
        for (int u4 = 0; u4 < 64; u4 += 4) {
            const float4 v0 = *reinterpret_cast<const float4*>(sn + 64 + u4 * 3);
            const float4 v1 = *reinterpret_cast<const float4*>(sn + 64 + u4 * 3 + 4);
            const float4 v2 = *reinterpret_cast<const float4*>(sn + 64 + u4 * 3 + 8);
            const float xs[12] = {v0.x, v0.y, v0.z, v0.w, v1.x, v1.y,
                                  v1.z, v1.w, v2.x, v2.y, v2.z, v2.w};
#pragma unroll
            for (int j = 0; j < 4; j++) {
                const float* wrow = w01 + (u4 + j) * 32;
#pragma unroll
                for (int w = 0; w < 32; w++) {
                    const float wg = wrow[w];
                    acc[w * 3 + 0] += xs[j * 3 + 0] * wg;
                    acc[w * 3 + 1] += xs[j * 3 + 1] * wg;
                    acc[w * 3 + 2] += xs[j * 3 + 2] * wg;
                }
            }
        }
#pragma unroll 1
        for (int u4 = 0; u4 < 32; u4 += 4) {
            const float4 v0 = *reinterpret_cast<const float4*>(sn + 256 + u4 * 3);
            const float4 v1 = *reinterpret_cast<const float4*>(sn + 256 + u4 * 3 + 4);
            const float4 v2 = *reinterpret_cast<const float4*>(sn + 256 + u4 * 3 + 8);
            const float xs[12] = {v0.x, v0.y, v0.z, v0.w, v1.x, v1.y,
                                  v1.z, v1.w, v2.x, v2.y, v2.z, v2.w};
#pragma unroll
            for (int j = 0; j < 4; j++) {
                const float* wrow = w11 + (u4 + j) * 32;
#pragma unroll
                for (int w = 0; w < 32; w++) {
                    const float wg = wrow[w];
                    acc[w * 3 + 0] += xs[j * 3 + 0] * wg;
                    acc[w * 3 + 1] += xs[j * 3 + 1] * wg;
                    acc[w * 3 + 2] += xs[j * 3 + 2] * wg;
                }
            }
        }
#pragma unroll
        for (int i4 = 0; i4 < 96; i4 += 4) {
            float4 o = *reinterpret_cast<const float4*>(on + 64 + i4);
            o.x += acc[i4] * sc;     o.y += acc[i4 + 1] * sc;
            o.z += acc[i4 + 2] * sc; o.w += acc[i4 + 3] * sc;
            *reinterpret_cast<float4*>(on + 64 + i4) = o;
        }
    }
}

// ---------------------------------------------------------------------------
extern "C" void kernel_launch(void* const* d_in, const int* in_sizes, int n_in,
                              void* d_out, int out_size) {
    const float* node_input = (const float*)d_in[0];
    const float* node_attr  = (const float*)d_in[1];
    const float* edge_attr  = (const float*)d_in[2];
    const float* elemb      = (const float*)d_in[3];
    const float* W_si0      = (const float*)d_in[4];
    const float* W_si1      = (const float*)d_in[5];
    const float* W_l1_0     = (const float*)d_in[6];
    const float* W_l1_1     = (const float*)d_in[7];
    const float* W_l2_00    = (const float*)d_in[8];
    const float* W_l2_10    = (const float*)d_in[9];
    const float* W_l2_01    = (const float*)d_in[10];
    const float* W_l2_11    = (const float*)d_in[11];
    const float* W_fc1      = (const float*)d_in[12];
    const float* W_fc2      = (const float*)d_in[13];
    const int*   esrc       = (const int*)d_in[14];
    const int*   edst       = (const int*)d_in[15];
    float* out = (float*)d_out;

    zero_s_kernel<<<2048, 256>>>();
    node_pre_kernel<<<(N_NODES + 255) / 256, 256>>>(node_input, node_attr,
                                                    W_si0, W_si1, W_l1_0,
                                                    W_l1_1, out);
    edge_kernel<<<N_EDGES / TE, 192>>>(elemb, edge_attr, esrc, edst,
                                       W_fc1, W_fc2);
    node_post_kernel<<<(N_NODES + 255) / 256, 256>>>(node_attr, W_l2_00,
                                                     W_l2_10, W_l2_01,
                                                     W_l2_11, out);
}

// round 3
// speedup vs baseline: 1.4841x; 1.4841x over previous
#include <cuda_runtime.h>

#define N_NODES 50000
#define N_EDGES 800000
#define NODE_F  160     // 64 scalar + 32*3 vector
#define S_F     384     // s0:64  s1:192  s2:96  s3:32
#define TE      16      // edges per block in edge kernel

// Scratch (device globals — no allocations allowed)
__device__ float g_l[N_NODES * NODE_F];
__device__ float g_s[N_NODES * S_F];
__device__ float g_fc2t[192 * 100];   // W_fc2 transposed: [t][k]

// Packed fp32x2 FMA (non-volatile: pure dataflow, let ptxas schedule)
#define FMA2(acc, ab, bb) \
  asm("fma.rn.f32x2 %0, %1, %2, %0;" : "+l"(acc) : "l"(ab), "l"(bb))

// ---------------------------------------------------------------------------
__global__ void zero_s_kernel() {
    const int n4 = N_NODES * S_F / 4;
    float4* p = reinterpret_cast<float4*>(g_s);
    float4 z = make_float4(0.f, 0.f, 0.f, 0.f);
    for (int i = blockIdx.x * blockDim.x + threadIdx.x; i < n4;
         i += gridDim.x * blockDim.x)
        p[i] = z;
}

__global__ void transpose_fc2_kernel(const float* __restrict__ W) {
    const int i = blockIdx.x * 256 + threadIdx.x;   // i = k*192 + t
    if (i < 192 * 100) {
        const int k = i / 192, t = i - k * 192;
        g_fc2t[t * 100 + k] = W[i];
    }
}

// ---------------------------------------------------------------------------
// Node pre-pass: thread-per-node, weights in smem, acc in registers.
__global__ void __launch_bounds__(256)
node_pre_kernel(const float* __restrict__ x,
                const float* __restrict__ attr,
                const float* __restrict__ Wsi0,
                const float* __restrict__ Wsi1,
                const float* __restrict__ Wl10,
                const float* __restrict__ Wl11,
                float* __restrict__ out) {
    __shared__ float wS0[4096], wL0[4096], wS1[1024], wL1[1024];
    const int t = threadIdx.x;
    for (int i = t; i < 4096; i += 256) { wS0[i] = Wsi0[i]; wL0[i] = Wl10[i]; }
    for (int i = t; i < 1024; i += 256) { wS1[i] = Wsi1[i]; wL1[i] = Wl11[i]; }
    __syncthreads();

    const int n = blockIdx.x * 256 + t;
    if (n >= N_NODES) return;
    const float a  = attr[n];
    const float sA = a * 0.125f;
    const float sV = a * 0.17677669529663689f;
    const float* xn = x   + (size_t)n * NODE_F;
    float* on       = out + (size_t)n * NODE_F;
    float* ln       = g_l + (size_t)n * NODE_F;

#pragma unroll 1
    for (int pass = 0; pass < 2; pass++) {
        const float* W = pass ? wL0 : wS0;
        float* dst     = pass ? ln  : on;
        float acc[64];
#pragma unroll
        for (int i = 0; i < 64; i++) acc[i] = 0.f;
#pragma unroll 1
        for (int u4 = 0; u4 < 64; u4 += 4) {
            const float4 xv = *reinterpret_cast<const float4*>(xn + u4);
            const float xs[4] = {xv.x, xv.y, xv.z, xv.w};
#pragma unroll
            for (int j = 0; j < 4; j++) {
                const float* wrow = W + (u4 + j) * 64;
#pragma unroll
                for (int tt = 0; tt < 64; tt++) acc[tt] += xs[j] * wrow[tt];
            }
        }
#pragma unroll
        for (int t4 = 0; t4 < 64; t4 += 4)
            *reinterpret_cast<float4*>(dst + t4) =
                make_float4(acc[t4] * sA, acc[t4 + 1] * sA,
                            acc[t4 + 2] * sA, acc[t4 + 3] * sA);
    }

#pragma unroll 1
    for (int pass = 0; pass < 2; pass++) {
        const float* W = pass ? wL1 : wS1;
        float* dst     = (pass ? ln : on) + 64;
        float acc[96];
#pragma unroll
        for (int i = 0; i < 96; i++) acc[i] = 0.f;
#pragma unroll 1
        for (int u4 = 0; u4 < 32; u4 += 4) {
            const float4 v0 = *reinterpret_cast<const float4*>(xn + 64 + u4 * 3);
            const float4 v1 = *reinterpret_cast<const float4*>(xn + 64 + u4 * 3 + 4);
            const float4 v2 = *reinterpret_cast<const float4*>(xn + 64 + u4 * 3 + 8);
            const float xs[12] = {v0.x, v0.y, v0.z, v0.w, v1.x, v1.y,
                                  v1.z, v1.w, v2.x, v2.y, v2.z, v2.w};
#pragma unroll
            for (int j = 0; j < 4; j++) {
                const float* wrow = W + (u4 + j) * 32;
#pragma unroll
                for (int w = 0; w < 32; w++) {
                    const float wg = wrow[w];
                    acc[w * 3 + 0] += xs[j * 3 + 0] * wg;
                    acc[w * 3 + 1] += xs[j * 3 + 1] * wg;
                    acc[w * 3 + 2] += xs[j * 3 + 2] * wg;
                }
            }
        }
#pragma unroll
        for (int i4 = 0; i4 < 96; i4 += 4)
            *reinterpret_cast<float4*>(dst + i4) =
                make_float4(acc[i4] * sV, acc[i4 + 1] * sV,
                            acc[i4 + 2] * sV, acc[i4 + 3] * sV);
    }
}

// ---------------------------------------------------------------------------
// Edge pass: Phase A (radial MLP layer 1), Phase B (layer 2, FFMA2-packed),
// Phase C (R1-proven warp-coalesced scalar REDs).
__global__ void __launch_bounds__(192)
edge_kernel(const float* __restrict__ elemb,
            const float* __restrict__ eattr,
            const int*   __restrict__ esrc,
            const int*   __restrict__ edst,
            const float* __restrict__ Wfc1) {
    __shared__ __align__(16) float sh_h[100][TE];
    __shared__ float sh_el[TE][10];
    __shared__ float sh_ea[TE][4];
    __shared__ int   sh_src[TE];
    __shared__ int   sh_dst[TE];

    const int t  = threadIdx.x;
    const int e0 = blockIdx.x * TE;

    for (int i = t; i < TE * 10; i += 192)
        sh_el[i / 10][i % 10] = elemb[e0 * 10 + i];
    if (t < TE * 4)
        sh_ea[t >> 2][t & 3] = eattr[e0 * 4 + t];
    if (t >= 64 && t < 64 + TE) {
        sh_src[t - 64] = esrc[e0 + t - 64];
        sh_dst[t - 64] = edst[e0 + t - 64];
    }
    __syncthreads();

    // Phase A: H = relu(elemb @ Wfc1 / sqrt(10)) * sqrt(2), layout [k][e]
    for (int idx = t; idx < 100 * TE; idx += 192) {
        const int e = idx & 15, k = idx >> 4;
        float acc = 0.f;
#pragma unroll
        for (int b = 0; b < 10; b++)
            acc += sh_el[e][b] * Wfc1[b * 100 + k];
        acc *= 0.31622776601683794f;
        sh_h[k][e] = fmaxf(acc, 0.f) * 1.4142135623730951f;
    }
    __syncthreads();

    // Phase B: w[e][t] = sum_k H[e][k] * Wfc2[k][t], packed 2 edges per FFMA2.
    unsigned long long acc2[8];
#pragma unroll
    for (int p = 0; p < 8; p++) acc2[p] = 0ull;
    const float* wrow = g_fc2t + t * 100;
#pragma unroll 2
    for (int k4 = 0; k4 < 100; k4 += 4) {
        const float4 w4 = *reinterpret_cast<const float4*>(wrow + k4);
        const float wfs[4] = {w4.x, w4.y, w4.z, w4.w};
#pragma unroll
        for (int j = 0; j < 4; j++) {
            unsigned long long wp;
            asm("mov.b64 %0, {%1, %1};" : "=l"(wp) : "f"(wfs[j]));
            const ulonglong2* hp =
                reinterpret_cast<const ulonglong2*>(sh_h[k4 + j]);
            const ulonglong2 q0 = hp[0], q1 = hp[1], q2 = hp[2], q3 = hp[3];
            FMA2(acc2[0], q0.x, wp); FMA2(acc2[1], q0.y, wp);
            FMA2(acc2[2], q1.x, wp); FMA2(acc2[3], q1.y, wp);
            FMA2(acc2[4], q2.x, wp); FMA2(acc2[5], q2.y, wp);
            FMA2(acc2[6], q3.x, wp); FMA2(acc2[7], q3.y, wp);
        }
    }
    float acc[TE];
#pragma unroll
    for (int p = 0; p < 8; p++)
        asm("mov.b64 {%0, %1}, %2;"
            : "=f"(acc[2 * p]), "=f"(acc[2 * p + 1]) : "l"(acc2[p]));

    const float SW = 0.025f;   // (1/sqrt(100)) * (1/sqrt(16))

    // Phase C (R1-proven): thread t = feature, warp-coalesced scalar REDs.
    if (t < 64) {
        const int j = t;
#pragma unroll 4
        for (int e = 0; e < TE; e++) {
            const int s = sh_src[e], d = sh_dst[e];
            const float y0 = g_l[s * NODE_F + j];
            atomicAdd(&g_s[d * S_F + j], acc[e] * SW * y0 * sh_ea[e][0]);
        }
    } else if (t < 128) {
        const int u = t - 64;
#pragma unroll 4
        for (int e = 0; e < TE; e++) {
            const int s = sh_src[e], d = sh_dst[e];
            const float y0 = g_l[s * NODE_F + u];
            const float base = acc[e] * SW * y0;
            float* p = &g_s[d * S_F + 64 + u * 3];
            atomicAdd(p + 0, base * sh_ea[e][1]);
            atomicAdd(p + 1, base * sh_ea[e][2]);
            atomicAdd(p + 2, base * sh_ea[e][3]);
        }
    } else if (t < 160) {
        const int u = t - 128;
#pragma unroll 4
        for (int e = 0; e < TE; e++) {
            const int s = sh_src[e], d = sh_dst[e];
            const float base = acc[e] * SW * sh_ea[e][0];
            const float* yl = &g_l[s * NODE_F + 64 + u * 3];
            float* p = &g_s[d * S_F + 256 + u * 3];
            atomicAdd(p + 0, base * yl[0]);
            atomicAdd(p + 1, base * yl[1]);
            atomicAdd(p + 2, base * yl[2]);
        }
    } else {
        const int u = t - 160;
#pragma unroll 4
        for (int e = 0; e < TE; e++) {
            const int s = sh_src[e], d = sh_dst[e];
            const float* yl = &g_l[s * NODE_F + 64 + u * 3];
            const float dotv = yl[0] * sh_ea[e][1] + yl[1] * sh_ea[e][2] +
                               yl[2] * sh_ea[e][3];
            atomicAdd(&g_s[d * S_F + 352 + u],
                      acc[e] * SW * dotv * 0.5773502691896258f);
        }
    }
}

// ---------------------------------------------------------------------------
// Node post-pass: thread-per-node, weights in smem, acc in registers.
__global__ void __launch_bounds__(256)
node_post_kernel(const float* __restrict__ attr,
                 const float* __restrict__ W00,
                 const float* __restrict__ W10,
                 const float* __restrict__ W01,
                 const float* __restrict__ W11,
                 float* __restrict__ out) {
    __shared__ float w00[4096], w10[2048], w01[2048], w11[1024];
    const int t = threadIdx.x;
    for (int i = t; i < 4096; i += 256) w00[i] = W00[i];
    for (int i = t; i < 2048; i += 256) { w10[i] = W10[i]; w01[i] = W01[i]; }
    for (int i = t; i < 1024; i += 256) w11[i] = W11[i];
    __syncthreads();

    const int n = blockIdx.x * 256 + t;
    if (n >= N_NODES) return;
    const float sc = attr[n] * 0.05103103630798288f;
    const float* sn = g_s + (size_t)n * S_F;
    float* on       = out + (size_t)n * NODE_F;

    {
        float acc[64];
#pragma unroll
        for (int i = 0; i < 64; i++) acc[i] = 0.f;
#pragma unroll 1
        for (int u4 = 0; u4 < 64; u4 += 4) {
            const float4 sv = *reinterpret_cast<const float4*>(sn + u4);
            const float xs[4] = {sv.x, sv.y, sv.z, sv.w};
#pragma unroll
            for (int j = 0; j < 4; j++) {
                const float* wrow = w00 + (u4 + j) * 64;
#pragma unroll
                for (int tt = 0; tt < 64; tt++) acc[tt] += xs[j] * wrow[tt];
            }
        }
#pragma unroll 1
        for (int u4 = 0; u4 < 32; u4 += 4) {
            const float4 sv = *reinterpret_cast<const float4*>(sn + 352 + u4);
            const float xs[4] = {sv.x, sv.y, sv.z, sv.w};
#pragma unroll
            for (int j = 0; j < 4; j++) {
                const float* wrow = w10 + (u4 + j) * 64;
#pragma unroll
                for (int tt = 0; tt < 64; tt++) acc[tt] += xs[j] * wrow[tt];
            }
        }
#pragma unroll
        for (int t4 = 0; t4 < 64; t4 += 4) {
            float4 o = *reinterpret_cast<const float4*>(on + t4);
            o.x += acc[t4] * sc;     o.y += acc[t4 + 1] * sc;
            o.z += acc[t4 + 2] * sc; o.w += acc[t4 + 3] * sc;
            *reinterpret_cast<float4*>(on + t4) = o;
        }
    }

    {
        float acc[96];
#pragma unroll
        for (int i = 0; i < 96; i++) acc[i] = 0.f;
#pragma unroll 1
        for (int u4 = 0; u4 < 64; u4 += 4) {
            const float4 v0 = *reinterpret_cast<const float4*>(sn + 64 + u4 * 3);
            const float4 v1 = *reinterpret_cast<const float4*>(sn + 64 + u4 * 3 + 4);
            const float4 v2 = *reinterpret_cast<const float4*>(sn + 64 + u4 * 3 + 8);
            const float xs[12] = {v0.x, v0.y, v0.z, v0.w, v1.x, v1.y,
                                  v1.z, v1.w, v2.x, v2.y, v2.z, v2.w};
#pragma unroll
            for (int j = 0; j < 4; j++) {
                const float* wrow = w01 + (u4 + j) * 32;
#pragma unroll
                for (int w = 0; w < 32; w++) {
                    const float wg = wrow[w];
                    acc[w * 3 + 0] += xs[j * 3 + 0] * wg;
                    acc[w * 3 + 1] += xs[j * 3 + 1] * wg;
                    acc[w * 3 + 2] += xs[j * 3 + 2] * wg;
                }
            }
        }
#pragma unroll 1
        for (int u4 = 0; u4 < 32; u4 += 4) {
            const float4 v0 = *reinterpret_cast<const float4*>(sn + 256 + u4 * 3);
            const float4 v1 = *reinterpret_cast<const float4*>(sn + 256 + u4 * 3 + 4);
            const float4 v2 = *reinterpret_cast<const float4*>(sn + 256 + u4 * 3 + 8);
            const float xs[12] = {v0.x, v0.y, v0.z, v0.w, v1.x, v1.y,
                                  v1.z, v1.w, v2.x, v2.y, v2.z, v2.w};
#pragma unroll
            for (int j = 0; j < 4; j++) {
                const float* wrow = w11 + (u4 + j) * 32;
#pragma unroll
                for (int w = 0; w < 32; w++) {
                    const float wg = wrow[w];
                    acc[w * 3 + 0] += xs[j * 3 + 0] * wg;
                    acc[w * 3 + 1] += xs[j * 3 + 1] * wg;
                    acc[w * 3 + 2] += xs[j * 3 + 2] * wg;
                }
            }
        }
#pragma unroll
        for (int i4 = 0; i4 < 96; i4 += 4) {
            float4 o = *reinterpret_cast<const float4*>(on + 64 + i4);
            o.x += acc[i4] * sc;     o.y += acc[i4 + 1] * sc;
            o.z += acc[i4 + 2] * sc; o.w += acc[i4 + 3] * sc;
            *reinterpret_cast<float4*>(on + 64 + i4) = o;
        }
    }
}

// ---------------------------------------------------------------------------
extern "C" void kernel_launch(void* const* d_in, const int* in_sizes, int n_in,
                              void* d_out, int out_size) {
    const float* node_input = (const float*)d_in[0];
    const float* node_attr  = (const float*)d_in[1];
    const float* edge_attr  = (const float*)d_in[2];
    const float* elemb      = (const float*)d_in[3];
    const float* W_si0      = (const float*)d_in[4];
    const float* W_si1      = (const float*)d_in[5];
    const float* W_l1_0     = (const float*)d_in[6];
    const float* W_l1_1     = (const float*)d_in[7];
    const float* W_l2_00    = (const float*)d_in[8];
    const float* W_l2_10    = (const float*)d_in[9];
    const float* W_l2_01    = (const float*)d_in[10];
    const float* W_l2_11    = (const float*)d_in[11];
    const float* W_fc1      = (const float*)d_in[12];
    const float* W_fc2      = (const float*)d_in[13];
    const int*   esrc       = (const int*)d_in[14];
    const int*   edst       = (const int*)d_in[15];
    float* out = (float*)d_out;

    zero_s_kernel<<<2048, 256>>>();
    transpose_fc2_kernel<<<(192 * 100 + 255) / 256, 256>>>(W_fc2);
    node_pre_kernel<<<(N_NODES + 255) / 256, 256>>>(node_input, node_attr,
                                                    W_si0, W_si1, W_l1_0,
                                                    W_l1_1, out);
    edge_kernel<<<N_EDGES / TE, 192>>>(elemb, edge_attr, esrc, edst, W_fc1);
    node_post_kernel<<<(N_NODES + 255) / 256, 256>>>(node_attr, W_l2_00,
                                                     W_l2_10, W_l2_01,
                                                     W_l2_11, out);
}

// round 5
// speedup vs baseline: 1.5045x; 1.0137x over previous
#include <cuda_runtime.h>

#define N_NODES 50000
#define N_EDGES 800000
#define NODE_F  160     // 64 scalar + 32*3 vector
#define S_F     384     // s0:64  s1:192  s2:96  s3:32
#define TE      16      // edges per block in edge kernel

// Scratch (device globals — no allocations allowed)
__device__ float g_l[N_NODES * NODE_F];
__device__ float g_s[N_NODES * S_F];
__device__ float g_fc2t[192 * 100];   // W_fc2 transposed: [t][k]
__device__ int   g_cnt[N_NODES];      // per-dst edge count
__device__ int   g_cur[N_NODES];      // scatter cursor (exclusive offsets)
__device__ int   g_ssrc[N_EDGES];     // src, sorted by dst
__device__ int   g_sdst[N_EDGES];     // dst, sorted
__device__ int   g_pei[N_EDGES];      // original edge index, sorted

// Packed fp32x2 FMA
#define FMA2(acc, ab, bb) \
  asm("fma.rn.f32x2 %0, %1, %2, %0;" : "+l"(acc) : "l"(ab), "l"(bb))

// ---------------------------------------------------------------------------
__global__ void zero_kernel() {
    const int n4 = N_NODES * S_F / 4;
    float4* p = reinterpret_cast<float4*>(g_s);
    const float4 z = make_float4(0.f, 0.f, 0.f, 0.f);
    const int gid = blockIdx.x * blockDim.x + threadIdx.x;
    for (int i = gid; i < n4; i += gridDim.x * blockDim.x) p[i] = z;
    for (int i = gid; i < N_NODES; i += gridDim.x * blockDim.x) g_cnt[i] = 0;
}

__global__ void transpose_fc2_kernel(const float* __restrict__ W) {
    const int i = blockIdx.x * 256 + threadIdx.x;   // i = k*192 + t
    if (i < 192 * 100) {
        const int k = i / 192, t = i - k * 192;
        g_fc2t[t * 100 + k] = W[i];
    }
}

__global__ void hist_kernel(const int* __restrict__ edst) {
    const int e = blockIdx.x * 256 + threadIdx.x;
    if (e < N_EDGES) atomicAdd(&g_cnt[edst[e]], 1);
}

// One block, 1024 threads: exclusive prefix sum of g_cnt -> g_cur
__global__ void scan_kernel() {
    __shared__ int part[1024];
    const int t = threadIdx.x;
    const int PER = (N_NODES + 1023) / 1024;   // 49
    const int base = t * PER;
    int sum = 0;
    for (int i = 0; i < PER; i++) {
        const int n = base + i;
        if (n < N_NODES) sum += g_cnt[n];
    }
    part[t] = sum;
    __syncthreads();
    for (int off = 1; off < 1024; off <<= 1) {
        int v = 0;
        if (t >= off) v = part[t - off];
        __syncthreads();
        if (t >= off) part[t] += v;
        __syncthreads();
    }
    int run = (t == 0) ? 0 : part[t - 1];
    for (int i = 0; i < PER; i++) {
        const int n = base + i;
        if (n < N_NODES) { g_cur[n] = run; run += g_cnt[n]; }
    }
}

__global__ void scatter_kernel(const int* __restrict__ esrc,
                               const int* __restrict__ edst) {
    const int e = blockIdx.x * 256 + threadIdx.x;
    if (e < N_EDGES) {
        const int d = edst[e];
        const int pos = atomicAdd(&g_cur[d], 1);
        g_ssrc[pos] = esrc[e];
        g_sdst[pos] = d;
        g_pei[pos]  = e;
    }
}

// ---------------------------------------------------------------------------
// Node pre-pass: thread-per-node, weights in smem, acc in registers.
__global__ void __launch_bounds__(256)
node_pre_kernel(const float* __restrict__ x,
                const float* __restrict__ attr,
                const float* __restrict__ Wsi0,
                const float* __restrict__ Wsi1,
                const float* __restrict__ Wl10,
                const float* __restrict__ Wl11,
                float* __restrict__ out) {
    __shared__ float wS0[4096], wL0[4096], wS1[1024], wL1[1024];
    const int t = threadIdx.x;
    for (int i = t; i < 4096; i += 256) { wS0[i] = Wsi0[i]; wL0[i] = Wl10[i]; }
    for (int i = t; i < 1024; i += 256) { wS1[i] = Wsi1[i]; wL1[i] = Wl11[i]; }
    __syncthreads();

    const int n = blockIdx.x * 256 + t;
    if (n >= N_NODES) return;
    const float a  = attr[n];
    const float sA = a * 0.125f;
    const float sV = a * 0.17677669529663689f;
    const float* xn = x   + (size_t)n * NODE_F;
    float* on       = out + (size_t)n * NODE_F;
    float* ln       = g_l + (size_t)n * NODE_F;

#pragma unroll 1
    for (int pass = 0; pass < 2; pass++) {
        const float* W = pass ? wL0 : wS0;
        float* dst     = pass ? ln  : on;
        float acc[64];
#pragma unroll
        for (int i = 0; i < 64; i++) acc[i] = 0.f;
#pragma unroll 1
        for (int u4 = 0; u4 < 64; u4 += 4) {
            const float4 xv = *reinterpret_cast<const float4*>(xn + u4);
            const float xs[4] = {xv.x, xv.y, xv.z, xv.w};
#pragma unroll
            for (int j = 0; j < 4; j++) {
                const float* wrow = W + (u4 + j) * 64;
#pragma unroll
                for (int tt = 0; tt < 64; tt++) acc[tt] += xs[j] * wrow[tt];
            }
        }
#pragma unroll
        for (int t4 = 0; t4 < 64; t4 += 4)
            *reinterpret_cast<float4*>(dst + t4) =
                make_float4(acc[t4] * sA, acc[t4 + 1] * sA,
                            acc[t4 + 2] * sA, acc[t4 + 3] * sA);
    }

#pragma unroll 1
    for (int pass = 0; pass < 2; pass++) {
        const float* W = pass ? wL1 : wS1;
        float* dst     = (pass ? ln : on) + 64;
        float acc[96];
#pragma unroll
        for (int i = 0; i < 96; i++) acc[i] = 0.f;
#pragma unroll 1
        for (int u4 = 0; u4 < 32; u4 += 4) {
            const float4 v0 = *reinterpret_cast<const float4*>(xn + 64 + u4 * 3);
            const float4 v1 = *reinterpret_cast<const float4*>(xn + 64 + u4 * 3 + 4);
            const float4 v2 = *reinterpret_cast<const float4*>(xn + 64 + u4 * 3 + 8);
            const float xs[12] = {v0.x, v0.y, v0.z, v0.w, v1.x, v1.y,
                                  v1.z, v1.w, v2.x, v2.y, v2.z, v2.w};
#pragma unroll
            for (int j = 0; j < 4; j++) {
                const float* wrow = W + (u4 + j) * 32;
#pragma unroll
                for (int w = 0; w < 32; w++) {
                    const float wg = wrow[w];
                    acc[w * 3 + 0] += xs[j * 3 + 0] * wg;
                    acc[w * 3 + 1] += xs[j * 3 + 1] * wg;
                    acc[w * 3 + 2] += xs[j * 3 + 2] * wg;
                }
            }
        }
#pragma unroll
        for (int i4 = 0; i4 < 96; i4 += 4)
            *reinterpret_cast<float4*>(dst + i4) =
                make_float4(acc[i4] * sV, acc[i4 + 1] * sV,
                            acc[i4 + 2] * sV, acc[i4 + 3] * sV);
    }
}

// ---------------------------------------------------------------------------
// Edge pass over dst-SORTED edges. Phase A: radial layer 1. Phase B: layer 2
// (2 features/thread, FFMA2). Phase C: register accumulation across same-dst
// runs, flush with coalesced REDs on dst change.
__global__ void __launch_bounds__(192)
edge_kernel(const float* __restrict__ elemb,
            const float* __restrict__ eattr,
            const float* __restrict__ Wfc1) {
    __shared__ __align__(16) float sh_h[100][TE];
    __shared__ float sh_w[192][TE + 1];   // +1 pad: conflict-free Phase C reads
    __shared__ float sh_el[TE][10];
    __shared__ float sh_ea[TE][4];
    __shared__ int   sh_src[TE];
    __shared__ int   sh_dst[TE];
    __shared__ int   sh_pei[TE];

    const int t  = threadIdx.x;
    const int e0 = blockIdx.x * TE;

    if (t < TE) {
        sh_src[t] = g_ssrc[e0 + t];
        sh_dst[t] = g_sdst[e0 + t];
        sh_pei[t] = g_pei[e0 + t];
    }
    __syncthreads();

    // Gather edge data via the sort permutation.
    // elemb: threads [0,160) — one (e,b) each. eattr: threads [128,192) — 64 values.
    if (t < TE * 10) {
        const int e = t / 10, b = t - e * 10;
        sh_el[e][b] = elemb[(size_t)sh_pei[e] * 10 + b];
    }
    if (t >= 128) {
        const int i = t - 128;               // [0,64)
        sh_ea[i >> 2][i & 3] = eattr[(size_t)sh_pei[i >> 2] * 4 + (i & 3)];
    }
    __syncthreads();

    // Phase A: H = relu(elemb @ Wfc1 / sqrt(10)) * sqrt(2), layout [k][e]
    for (int idx = t; idx < 100 * TE; idx += 192) {
        const int e = idx & 15, k = idx >> 4;
        float acc = 0.f;
#pragma unroll
        for (int b = 0; b < 10; b++)
            acc += sh_el[e][b] * Wfc1[b * 100 + k];
        acc *= 0.31622776601683794f;
        sh_h[k][e] = fmaxf(acc, 0.f) * 1.4142135623730951f;
    }
    __syncthreads();

    // Phase B: threads 0..95 compute features t and t+96 for all 16 edges.
    if (t < 96) {
        unsigned long long accA[8], accB[8];
#pragma unroll
        for (int p = 0; p < 8; p++) { accA[p] = 0ull; accB[p] = 0ull; }
        const float* wrA = g_fc2t + t * 100;
        const float* wrB = g_fc2t + (t + 96) * 100;
#pragma unroll 5
        for (int k4 = 0; k4 < 100; k4 += 4) {
            const float4 wa4 = *reinterpret_cast<const float4*>(wrA + k4);
            const float4 wb4 = *reinterpret_cast<const float4*>(wrB + k4);
            const float was[4] = {wa4.x, wa4.y, wa4.z, wa4.w};
            const float wbs[4] = {wb4.x, wb4.y, wb4.z, wb4.w};
#pragma unroll
            for (int j = 0; j < 4; j++) {
                unsigned long long wpA, wpB;
                asm("mov.b64 %0, {%1, %1};" : "=l"(wpA) : "f"(was[j]));
                asm("mov.b64 %0, {%1, %1};" : "=l"(wpB) : "f"(wbs[j]));
                const ulonglong2* hp =
                    reinterpret_cast<const ulonglong2*>(sh_h[k4 + j]);
                const ulonglong2 q0 = hp[0], q1 = hp[1], q2 = hp[2], q3 = hp[3];
                FMA2(accA[0], q0.x, wpA); FMA2(accB[0], q0.x, wpB);
                FMA2(accA[1], q0.y, wpA); FMA2(accB[1], q0.y, wpB);
                FMA2(accA[2], q1.x, wpA); FMA2(accB[2], q1.x, wpB);
                FMA2(accA[3], q1.y, wpA); FMA2(accB[3], q1.y, wpB);
                FMA2(accA[4], q2.x, wpA); FMA2(accB[4], q2.x, wpB);
                FMA2(accA[5], q2.y, wpA); FMA2(accB[5], q2.y, wpB);
                FMA2(accA[6], q3.x, wpA); FMA2(accB[6], q3.x, wpB);
                FMA2(accA[7], q3.y, wpA); FMA2(accB[7], q3.y, wpB);
            }
        }
        const float SW = 0.025f;   // (1/sqrt(100)) * (1/sqrt(16))
#pragma unroll
        for (int p = 0; p < 8; p++) {
            float lo, hi;
            asm("mov.b64 {%0, %1}, %2;" : "=f"(lo), "=f"(hi) : "l"(accA[p]));
            sh_w[t][2 * p]     = lo * SW;
            sh_w[t][2 * p + 1] = hi * SW;
            asm("mov.b64 {%0, %1}, %2;" : "=f"(lo), "=f"(hi) : "l"(accB[p]));
            sh_w[t + 96][2 * p]     = lo * SW;
            sh_w[t + 96][2 * p + 1] = hi * SW;
        }
    }
    __syncthreads();

    // Phase C: accumulate across same-dst runs (dsts sorted), flush on change.
    if (t < 64) {
        float a0 = 0.f;
#pragma unroll
        for (int e = 0; e < TE; e++) {
            const int s = sh_src[e];
            const float y0 = g_l[(size_t)s * NODE_F + t];
            a0 = fmaf(sh_w[t][e] * sh_ea[e][0], y0, a0);
            if (e == TE - 1 || sh_dst[e + 1] != sh_dst[e]) {
                atomicAdd(&g_s[(size_t)sh_dst[e] * S_F + t], a0);
                a0 = 0.f;
            }
        }
    } else if (t < 128) {
        const int u = t - 64;
        float a1 = 0.f, a2 = 0.f, a3 = 0.f;
#pragma unroll
        for (int e = 0; e < TE; e++) {
            const int s = sh_src[e];
            const float base = sh_w[t][e] * g_l[(size_t)s * NODE_F + u];
            a1 = fmaf(base, sh_ea[e][1], a1);
            a2 = fmaf(base, sh_ea[e][2], a2);
            a3 = fmaf(base, sh_ea[e][3], a3);
            if (e == TE - 1 || sh_dst[e + 1] != sh_dst[e]) {
                float* p = &g_s[(size_t)sh_dst[e] * S_F + 64 + u * 3];
                atomicAdd(p + 0, a1);
                atomicAdd(p + 1, a2);
                atomicAdd(p + 2, a3);
                a1 = a2 = a3 = 0.f;
            }
        }
    } else if (t < 160) {
        const int u = t - 128;
        float a1 = 0.f, a2 = 0.f, a3 = 0.f;
#pragma unroll
        for (int e = 0; e < TE; e++) {
            const int s = sh_src[e];
            const float base = sh_w[t][e] * sh_ea[e][0];
            const float* yl = &g_l[(size_t)s * NODE_F + 64 + u * 3];
            a1 = fmaf(base, yl[0], a1);
            a2 = fmaf(base, yl[1], a2);
            a3 = fmaf(base, yl[2], a3);
            if (e == TE - 1 || sh_dst[e + 1] != sh_dst[e]) {
                float* p = &g_s[(size_t)sh_dst[e] * S_F + 256 + u * 3];
                atomicAdd(p + 0, a1);
                atomicAdd(p + 1, a2);
                atomicAdd(p + 2, a3);
                a1 = a2 = a3 = 0.f;
            }
        }
    } else {
        const int u = t - 160;
        float a0 = 0.f;
#pragma unroll
        for (int e = 0; e < TE; e++) {
            const int s = sh_src[e];
            const float* yl = &g_l[(size_t)s * NODE_F + 64 + u * 3];
            const float dotv = yl[0] * sh_ea[e][1] + yl[1] * sh_ea[e][2] +
                               yl[2] * sh_ea[e][3];
            a0 = fmaf(sh_w[t][e] * dotv, 0.5773502691896258f, a0);
            if (e == TE - 1 || sh_dst[e + 1] != sh_dst[e]) {
                atomicAdd(&g_s[(size_t)sh_dst[e] * S_F + 352 + u], a0);
                a0 = 0.f;
            }
        }
    }
}

// ---------------------------------------------------------------------------
// Node post-pass: thread-per-node, weights in smem, acc in registers.
__global__ void __launch_bounds__(256)
node_post_kernel(const float* __restrict__ attr,
                 const float* __restrict__ W00,
                 const float* __restrict__ W10,
                 const float* __restrict__ W01,
                 const float* __restrict__ W11,
                 float* __restrict__ out) {
    __shared__ float w00[4096], w10[2048], w01[2048], w11[1024];
    const int t = threadIdx.x;
    for (int i = t; i < 4096; i += 256) w00[i] = W00[i];
    for (int i = t; i < 2048; i += 256) { w10[i] = W10[i]; w01[i] = W01[i]; }
    for (int i = t; i < 1024; i += 256) w11[i] = W11[i];
    __syncthreads();

    const int n = blockIdx.x * 256 + t;
    if (n >= N_NODES) return;
    const float sc = attr[n] * 0.05103103630798288f;
    const float* sn = g_s + (size_t)n * S_F;
    float* on       = out + (size_t)n * NODE_F;

    {
        float acc[64];
#pragma unroll
        for (int i = 0; i < 64; i++) acc[i] = 0.f;
#pragma unroll 1
        for (int u4 = 0; u4 < 64; u4 += 4) {
            const float4 sv = *reinterpret_cast<const float4*>(sn + u4);
            const float xs[4] = {sv.x, sv.y, sv.z, sv.w};
#pragma unroll
            for (int j = 0; j < 4; j++) {
                const float* wrow = w00 + (u4 + j) * 64;
#pragma unroll
                for (int tt = 0; tt < 64; tt++) acc[tt] += xs[j] * wrow[tt];
            }
        }
#pragma unroll 1
        for (int u4 = 0; u4 < 32; u4 += 4) {
            const float4 sv = *reinterpret_cast<const float4*>(sn + 352 + u4);
            const float xs[4] = {sv.x, sv.y, sv.z, sv.w};
#pragma unroll
            for (int j = 0; j < 4; j++) {
                const float* wrow = w10 + (u4 + j) * 64;
#pragma unroll
                for (int tt = 0; tt < 64; tt++) acc[tt] += xs[j] * wrow[tt];
            }
        }
#pragma unroll
        for (int t4 = 0; t4 < 64; t4 += 4) {
            float4 o = *reinterpret_cast<const float4*>(on + t4);
            o.x += acc[t4] * sc;     o.y += acc[t4 + 1] * sc;
            o.z += acc[t4 + 2] * sc; o.w += acc[t4 + 3] * sc;
            *reinterpret_cast<float4*>(on + t4) = o;
        }
    }

    {
        float acc[96];
#pragma unroll
        for (int i = 0; i < 96; i++) acc[i] = 0.f;
#pragma unroll 1
        for (int u4 = 0; u4 < 64; u4 += 4) {
            const float4 v0 = *reinterpret_cast<const float4*>(sn + 64 + u4 * 3);
            const float4 v1 = *reinterpret_cast<const float4*>(sn + 64 + u4 * 3 + 4);
            const float4 v2 = *reinterpret_cast<const float4*>(sn + 64 + u4 * 3 + 8);
            const float xs[12] = {v0.x, v0.y, v0.z, v0.w, v1.x, v1.y,
                                  v1.z, v1.w, v2.x, v2.y, v2.z, v2.w};
#pragma unroll
            for (int j = 0; j < 4; j++) {
                const float* wrow = w01 + (u4 + j) * 32;
#pragma unroll
                for (int w = 0; w < 32; w++) {
                    const float wg = wrow[w];
                    acc[w * 3 + 0] += xs[j * 3 + 0] * wg;
                    acc[w * 3 + 1] += xs[j * 3 + 1] * wg;
                    acc[w * 3 + 2] += xs[j * 3 + 2] * wg;
                }
            }
        }
#pragma unroll 1
        for (int u4 = 0; u4 < 32; u4 += 4) {
            const float4 v0 = *reinterpret_cast<const float4*>(sn + 256 + u4 * 3);
            const float4 v1 = *reinterpret_cast<const float4*>(sn + 256 + u4 * 3 + 4);
            const float4 v2 = *reinterpret_cast<const float4*>(sn + 256 + u4 * 3 + 8);
            const float xs[12] = {v0.x, v0.y, v0.z, v0.w, v1.x, v1.y,
                                  v1.z, v1.w, v2.x, v2.y, v2.z, v2.w};
#pragma unroll
            for (int j = 0; j < 4; j++) {
                const float* wrow = w11 + (u4 + j) * 32;
#pragma unroll
                for (int w = 0; w < 32; w++) {
                    const float wg = wrow[w];
                    acc[w * 3 + 0] += xs[j * 3 + 0] * wg;
                    acc[w * 3 + 1] += xs[j * 3 + 1] * wg;
                    acc[w * 3 + 2] += xs[j * 3 + 2] * wg;
                }
            }
        }
#pragma unroll
        for (int i4 = 0; i4 < 96; i4 += 4) {
            float4 o = *reinterpret_cast<const float4*>(on + 64 + i4);
            o.x += acc[i4] * sc;     o.y += acc[i4 + 1] * sc;
            o.z += acc[i4 + 2] * sc; o.w += acc[i4 + 3] * sc;
            *reinterpret_cast<float4*>(on + 64 + i4) = o;
        }
    }
}

// ---------------------------------------------------------------------------
extern "C" void kernel_launch(void* const* d_in, const int* in_sizes, int n_in,
                              void* d_out, int out_size) {
    const float* node_input = (const float*)d_in[0];
    const float* node_attr  = (const float*)d_in[1];
    const float* edge_attr  = (const float*)d_in[2];
    const float* elemb      = (const float*)d_in[3];
    const float* W_si0      = (const float*)d_in[4];
    const float* W_si1      = (const float*)d_in[5];
    const float* W_l1_0     = (const float*)d_in[6];
    const float* W_l1_1     = (const float*)d_in[7];
    const float* W_l2_00    = (const float*)d_in[8];
    const float* W_l2_10    = (const float*)d_in[9];
    const float* W_l2_01    = (const float*)d_in[10];
    const float* W_l2_11    = (const float*)d_in[11];
    const float* W_fc1      = (const float*)d_in[12];
    const float* W_fc2      = (const float*)d_in[13];
    const int*   esrc       = (const int*)d_in[14];
    const int*   edst       = (const int*)d_in[15];
    float* out = (float*)d_out;

    zero_kernel<<<2048, 256>>>();
    transpose_fc2_kernel<<<(192 * 100 + 255) / 256, 256>>>(W_fc2);
    hist_kernel<<<(N_EDGES + 255) / 256, 256>>>(edst);
    scan_kernel<<<1, 1024>>>();
    scatter_kernel<<<(N_EDGES + 255) / 256, 256>>>(esrc, edst);
    node_pre_kernel<<<(N_NODES + 255) / 256, 256>>>(node_input, node_attr,
                                                    W_si0, W_si1, W_l1_0,
                                                    W_l1_1, out);
    edge_kernel<<<N_EDGES / TE, 192>>>(elemb, edge_attr, W_fc1);
    node_post_kernel<<<(N_NODES + 255) / 256, 256>>>(node_attr, W_l2_00,
                                                     W_l2_10, W_l2_01,
                                                     W_l2_11, out);
}

// round 7
// speedup vs baseline: 1.8673x; 1.2412x over previous
#include <cuda_runtime.h>
#include <cuda_bf16.h>
#include <cstdint>

#define N_NODES 50000
#define N_EDGES 800000
#define NODE_F  160     // 64 scalar + 32*3 vector
#define S_F     384     // s0:64  s1:192  s2:96  s3:32
#define TE      16      // edges per block in scatter kernel
#define ETG     128     // edges per tile in GEMM kernel
#define KP      112     // K padded 100 -> 112 (7 x k16)
#define KROW    120     // smem/global row stride in bf16 elems (240B, 16B mult)
#define NW      192     // w features

// Scratch (device globals — no allocations allowed)
__device__ float g_l[N_NODES * NODE_F];
__device__ float g_s[N_NODES * S_F];
__device__ float g_w[(size_t)N_EDGES * NW];   // chunk-major: [c][e][32]
__device__ uint4 g_Bhi[(NW * KROW * 2) / 16]; // Wfc2^T hi: [n][KROW] bf16
__device__ uint4 g_Blo[(NW * KROW * 2) / 16]; // Wfc2^T lo
__device__ int   g_cnt[N_NODES];
__device__ int   g_cur[N_NODES];
__device__ int   g_ssrc[N_EDGES];
__device__ int   g_sdst[N_EDGES];
__device__ int   g_pei[N_EDGES];

__device__ __forceinline__ uint32_t smem_u32(const void* p) {
    uint32_t a;
    asm("{ .reg .u64 t; cvta.to.shared.u64 t, %1; cvt.u32.u64 %0, t; }"
        : "=r"(a) : "l"(p));
    return a;
}

#define LDSM_X4(r, p) \
  asm volatile("ldmatrix.sync.aligned.m8n8.x4.shared.b16 {%0,%1,%2,%3}, [%4];" \
      : "=r"((r)[0]), "=r"((r)[1]), "=r"((r)[2]), "=r"((r)[3]) : "r"(p))

#define MMA_BF16(d, a, b0, b1) \
  asm volatile("mma.sync.aligned.m16n8k16.row.col.f32.bf16.bf16.f32 " \
      "{%0,%1,%2,%3}, {%4,%5,%6,%7}, {%8,%9}, {%0,%1,%2,%3};" \
      : "+f"((d)[0]), "+f"((d)[1]), "+f"((d)[2]), "+f"((d)[3]) \
      : "r"((a)[0]), "r"((a)[1]), "r"((a)[2]), "r"((a)[3]), "r"(b0), "r"(b1))

// Dynamic smem layout for gemm_kernel (bytes)
#define SM_A_HI 0
#define SM_A_LO (SM_A_HI + ETG * KROW * 2)          // 30720
#define SM_B_HI (SM_A_LO + ETG * KROW * 2)          // 61440
#define SM_B_LO (SM_B_HI + NW * KROW * 2)           // 107520
#define SM_WFC1 (SM_B_LO + NW * KROW * 2)           // 153600
#define SM_TOTAL (SM_WFC1 + 4096)                   // 157696

// ---------------------------------------------------------------------------
__global__ void zero_kernel() {
    const int n4 = N_NODES * S_F / 4;
    float4* p = reinterpret_cast<float4*>(g_s);
    const float4 z = make_float4(0.f, 0.f, 0.f, 0.f);
    const int gid = blockIdx.x * blockDim.x + threadIdx.x;
    for (int i = gid; i < n4; i += gridDim.x * blockDim.x) p[i] = z;
    for (int i = gid; i < N_NODES; i += gridDim.x * blockDim.x) g_cnt[i] = 0;
}

// Split Wfc2 into bf16 hi/lo, layout [n][KROW] (n = output feature, k padded)
__global__ void split_fc2_kernel(const float* __restrict__ W) {
    const int i = blockIdx.x * 256 + threadIdx.x;
    if (i >= NW * KROW) return;
    const int n = i / KROW, k = i - n * KROW;
    const float v = (k < 100) ? W[k * NW + n] : 0.f;
    const __nv_bfloat16 hb = __float2bfloat16(v);
    const __nv_bfloat16 lb = __float2bfloat16(v - __bfloat162float(hb));
    reinterpret_cast<__nv_bfloat16*>(g_Bhi)[i] = hb;
    reinterpret_cast<__nv_bfloat16*>(g_Blo)[i] = lb;
}

__global__ void hist_kernel(const int* __restrict__ edst) {
    const int e = blockIdx.x * 256 + threadIdx.x;
    if (e < N_EDGES) atomicAdd(&g_cnt[edst[e]], 1);
}

__global__ void scan_kernel() {
    __shared__ int part[1024];
    const int t = threadIdx.x;
    const int PER = (N_NODES + 1023) / 1024;
    const int base = t * PER;
    int sum = 0;
    for (int i = 0; i < PER; i++) {
        const int n = base + i;
        if (n < N_NODES) sum += g_cnt[n];
    }
    part[t] = sum;
    __syncthreads();
    for (int off = 1; off < 1024; off <<= 1) {
        int v = 0;
        if (t >= off) v = part[t - off];
        __syncthreads();
        if (t >= off) part[t] += v;
        __syncthreads();
    }
    int run = (t == 0) ? 0 : part[t - 1];
    for (int i = 0; i < PER; i++) {
        const int n = base + i;
        if (n < N_NODES) { g_cur[n] = run; run += g_cnt[n]; }
    }
}

__global__ void scatter_kernel(const int* __restrict__ esrc,
                               const int* __restrict__ edst) {
    const int e = blockIdx.x * 256 + threadIdx.x;
    if (e < N_EDGES) {
        const int d = edst[e];
        const int pos = atomicAdd(&g_cur[d], 1);
        g_ssrc[pos] = esrc[e];
        g_sdst[pos] = d;
        g_pei[pos]  = e;
    }
}

// ---------------------------------------------------------------------------
// GEMM: per 128-edge tile, H (fp32, scalar) -> bf16 hi/lo -> 3-pass bf16
// mma.sync (HMMA tensor path) -> w[128][192] -> g_w chunk-major.
__global__ void __launch_bounds__(512, 1)
gemm_kernel(const float* __restrict__ elemb,
            const float* __restrict__ Wfc1) {
    extern __shared__ char smem[];
    const uint32_t sb = smem_u32(smem);
    const int t = threadIdx.x;
    const int e0 = blockIdx.x * ETG;

    // Stage Wfc1, copy B hi/lo, zero A hi/lo
    float* sW1 = reinterpret_cast<float*>(smem + SM_WFC1);
    for (int i = t; i < 1000; i += 512) sW1[i] = Wfc1[i];
    {
        uint4* bh = reinterpret_cast<uint4*>(smem + SM_B_HI);
        uint4* bl = reinterpret_cast<uint4*>(smem + SM_B_LO);
        const int nB = NW * KROW * 2 / 16;   // 2880
        for (int i = t; i < nB; i += 512) { bh[i] = g_Bhi[i]; bl[i] = g_Blo[i]; }
        uint4* az = reinterpret_cast<uint4*>(smem + SM_A_HI);
        const uint4 z = make_uint4(0, 0, 0, 0);
        const int nA = ETG * KROW * 2 * 2 / 16;  // hi+lo together: 3840
        for (int i = t; i < nA; i += 512) az[i] = z;
    }

    // Phase 1: H rows. 4 threads per edge, 25 features each.
    {
        const int e = t >> 2, q = t & 3, fb = q * 25;
        const int pei = g_pei[e0 + e];
        float el[10];
        const float* er = elemb + (size_t)pei * 10;
#pragma unroll
        for (int b = 0; b < 10; b++) el[b] = er[b];
        __syncthreads();   // covers sW1 + A-zero + B-copy

        float h[25];
#pragma unroll
        for (int i = 0; i < 25; i++) h[i] = 0.f;
#pragma unroll
        for (int b = 0; b < 10; b++) {
            const float eb = el[b];
            const float* wr = sW1 + b * 100 + fb;
#pragma unroll
            for (int i = 0; i < 25; i++) h[i] = fmaf(eb, wr[i], h[i]);
        }
        __nv_bfloat16* ah = reinterpret_cast<__nv_bfloat16*>(smem + SM_A_HI) +
                            e * KROW + fb;
        __nv_bfloat16* al = reinterpret_cast<__nv_bfloat16*>(smem + SM_A_LO) +
                            e * KROW + fb;
#pragma unroll
        for (int i = 0; i < 25; i++) {
            const float f = fmaxf(h[i] * 0.31622776601683794f, 0.f) *
                            1.4142135623730951f;
            const __nv_bfloat16 hb = __float2bfloat16(f);
            ah[i] = hb;
            al[i] = __float2bfloat16(f - __bfloat162float(hb));
        }
    }
    __syncthreads();

    // Phase 2: mma. Warp wid: m-tile mt = wid&7 (rows 16*mt), n-half nh = wid>>3.
    const int wid = t >> 5, lane = t & 31;
    const int mt = wid & 7, nh = wid >> 3;

    float acc[12][4];
#pragma unroll
    for (int j = 0; j < 12; j++)
#pragma unroll
        for (int r = 0; r < 4; r++) acc[j][r] = 0.f;

    // A lane pointer: row = 16*mt + (lane&15), col = (lane>>4)*8 (+ kb)
    const uint32_t aoff =
        ((mt * 16 + (lane & 15)) * KROW + ((lane >> 4) << 3)) * 2;
    // B lane pointer parts: row offset within pair-of-ntiles, col 0/8
    const uint32_t brow = (lane & 7) + ((lane >> 4) << 3);
    const uint32_t bcol = ((lane >> 3) & 1) << 3;

#pragma unroll
    for (int k = 0; k < 7; k++) {
        const uint32_t kb = k << 4;
        uint32_t ah[4], al[4];
        LDSM_X4(ah, sb + SM_A_HI + aoff + kb * 2);
        LDSM_X4(al, sb + SM_A_LO + aoff + kb * 2);
#pragma unroll
        for (int j = 0; j < 12; j += 2) {
            const uint32_t nb = nh * 96 + j * 8;
            const uint32_t bo = ((nb + brow) * KROW + kb + bcol) * 2;
            uint32_t bh[4], bl[4];
            LDSM_X4(bh, sb + SM_B_HI + bo);
            LDSM_X4(bl, sb + SM_B_LO + bo);
            MMA_BF16(acc[j],     ah, bh[0], bh[1]);
            MMA_BF16(acc[j],     ah, bl[0], bl[1]);
            MMA_BF16(acc[j],     al, bh[0], bh[1]);
            MMA_BF16(acc[j + 1], ah, bh[2], bh[3]);
            MMA_BF16(acc[j + 1], ah, bl[2], bl[3]);
            MMA_BF16(acc[j + 1], al, bh[2], bh[3]);
        }
    }
    __syncthreads();   // all smem reads done; reuse smem as w staging

    // Phase 3: accum -> smem w[128][192] -> g_w chunk-major (coalesced)
    {
        float* ws = reinterpret_cast<float*>(smem);
        const int r0 = mt * 16 + (lane >> 2);
        const int c0 = 2 * (lane & 3);
#pragma unroll
        for (int j = 0; j < 12; j++) {
            const int cb = nh * 96 + j * 8 + c0;
            *reinterpret_cast<float2*>(ws + r0 * NW + cb) =
                make_float2(acc[j][0], acc[j][1]);
            *reinterpret_cast<float2*>(ws + (r0 + 8) * NW + cb) =
                make_float2(acc[j][2], acc[j][3]);
        }
        __syncthreads();
#pragma unroll
        for (int it = 0; it < 48; it++) {
            const int idx = it * 512 + t;        // 24576 total
            const int c = idx >> 12, rem = idx & 4095;
            const int e = rem >> 5, m = rem & 31;
            g_w[(size_t)c * ((size_t)N_EDGES * 32) + (size_t)(e0 + e) * 32 + m] =
                ws[e * NW + c * 32 + m];
        }
    }
}

// ---------------------------------------------------------------------------
// Node pre-pass: thread-per-node, weights in smem, acc in registers.
__global__ void __launch_bounds__(256)
node_pre_kernel(const float* __restrict__ x,
                const float* __restrict__ attr,
                const float* __restrict__ Wsi0,
                const float* __restrict__ Wsi1,
                const float* __restrict__ Wl10,
                const float* __restrict__ Wl11,
                float* __restrict__ out) {
    __shared__ float wS0[4096], wL0[4096], wS1[1024], wL1[1024];
    const int t = threadIdx.x;
    for (int i = t; i < 4096; i += 256) { wS0[i] = Wsi0[i]; wL0[i] = Wl10[i]; }
    for (int i = t; i < 1024; i += 256) { wS1[i] = Wsi1[i]; wL1[i] = Wl11[i]; }
    __syncthreads();

    const int n = blockIdx.x * 256 + t;
    if (n >= N_NODES) return;
    const float a  = attr[n];
    const float sA = a * 0.125f;
    const float sV = a * 0.17677669529663689f;
    const float* xn = x   + (size_t)n * NODE_F;
    float* on       = out + (size_t)n * NODE_F;
    float* ln       = g_l + (size_t)n * NODE_F;

#pragma unroll 1
    for (int pass = 0; pass < 2; pass++) {
        const float* W = pass ? wL0 : wS0;
        float* dst     = pass ? ln  : on;
        float acc[64];
#pragma unroll
        for (int i = 0; i < 64; i++) acc[i] = 0.f;
#pragma unroll 1
        for (int u4 = 0; u4 < 64; u4 += 4) {
            const float4 xv = *reinterpret_cast<const float4*>(xn + u4);
            const float xs[4] = {xv.x, xv.y, xv.z, xv.w};
#pragma unroll
            for (int j = 0; j < 4; j++) {
                const float* wrow = W + (u4 + j) * 64;
#pragma unroll
                for (int tt = 0; tt < 64; tt++) acc[tt] += xs[j] * wrow[tt];
            }
        }
#pragma unroll
        for (int t4 = 0; t4 < 64; t4 += 4)
            *reinterpret_cast<float4*>(dst + t4) =
                make_float4(acc[t4] * sA, acc[t4 + 1] * sA,
                            acc[t4 + 2] * sA, acc[t4 + 3] * sA);
    }

#pragma unroll 1
    for (int pass = 0; pass < 2; pass++) {
        const float* W = pass ? wL1 : wS1;
        float* dst     = (pass ? ln : on) + 64;
        float acc[96];
#pragma unroll
        for (int i = 0; i < 96; i++) acc[i] = 0.f;
#pragma unroll 1
        for (int u4 = 0; u4 < 32; u4 += 4) {
            const float4 v0 = *reinterpret_cast<const float4*>(xn + 64 + u4 * 3);
            const float4 v1 = *reinterpret_cast<const float4*>(xn + 64 + u4 * 3 + 4);
            const float4 v2 = *reinterpret_cast<const float4*>(xn + 64 + u4 * 3 + 8);
            const float xs[12] = {v0.x, v0.y, v0.z, v0.w, v1.x, v1.y,
                                  v1.z, v1.w, v2.x, v2.y, v2.z, v2.w};
#pragma unroll
            for (int j = 0; j < 4; j++) {
                const float* wrow = W + (u4 + j) * 32;
#pragma unroll
                for (int w = 0; w < 32; w++) {
                    const float wg = wrow[w];
                    acc[w * 3 + 0] += xs[j * 3 + 0] * wg;
                    acc[w * 3 + 1] += xs[j * 3 + 1] * wg;
                    acc[w * 3 + 2] += xs[j * 3 + 2] * wg;
                }
            }
        }
#pragma unroll
        for (int i4 = 0; i4 < 96; i4 += 4)
            *reinterpret_cast<float4*>(dst + i4) =
                make_float4(acc[i4] * sV, acc[i4 + 1] * sV,
                            acc[i4 + 2] * sV, acc[i4 + 3] * sV);
    }
}

// ---------------------------------------------------------------------------
// Scatter over dst-SORTED edges: coalesced w loads, run accumulation, RED flush.
__global__ void __launch_bounds__(192)
scatter_edge_kernel(const float* __restrict__ eattr) {
    __shared__ float sh_ea[TE][4];
    __shared__ int   sh_src[TE];
    __shared__ int   sh_dst[TE];
    __shared__ int   sh_pei[TE];

    const int t  = threadIdx.x;
    const int e0 = blockIdx.x * TE;

    if (t < TE) {
        sh_src[t] = g_ssrc[e0 + t];
        sh_dst[t] = g_sdst[e0 + t];
        sh_pei[t] = g_pei[e0 + t];
    }
    __syncthreads();
    if (t >= 128) {
        const int i = t - 128;   // [0,64)
        sh_ea[i >> 2][i & 3] = eattr[(size_t)sh_pei[i >> 2] * 4 + (i & 3)];
    }

    float lw[TE];
    {
        const float SW = 0.025f;   // (1/sqrt(100)) * (1/sqrt(16))
        const float* base = g_w + (size_t)(t >> 5) * ((size_t)N_EDGES * 32) +
                            (size_t)e0 * 32 + (t & 31);
#pragma unroll
        for (int e = 0; e < TE; e++) lw[e] = base[e * 32] * SW;
    }
    __syncthreads();

    if (t < 64) {
        float a0 = 0.f;
#pragma unroll
        for (int e = 0; e < TE; e++) {
            const int s = sh_src[e];
            const float y0 = g_l[(size_t)s * NODE_F + t];
            a0 = fmaf(lw[e] * sh_ea[e][0], y0, a0);
            if (e == TE - 1 || sh_dst[e + 1] != sh_dst[e]) {
                atomicAdd(&g_s[(size_t)sh_dst[e] * S_F + t], a0);
                a0 = 0.f;
            }
        }
    } else if (t < 128) {
        const int u = t - 64;
        float a1 = 0.f, a2 = 0.f, a3 = 0.f;
#pragma unroll
        for (int e = 0; e < TE; e++) {
            const int s = sh_src[e];
            const float base = lw[e] * g_l[(size_t)s * NODE_F + u];
            a1 = fmaf(base, sh_ea[e][1], a1);
            a2 = fmaf(base, sh_ea[e][2], a2);
            a3 = fmaf(base, sh_ea[e][3], a3);
            if (e == TE - 1 || sh_dst[e + 1] != sh_dst[e]) {
                float* p = &g_s[(size_t)sh_dst[e] * S_F + 64 + u * 3];
                atomicAdd(p + 0, a1);
                atomicAdd(p + 1, a2);
                atomicAdd(p + 2, a3);
                a1 = a2 = a3 = 0.f;
            }
        }
    } else if (t < 160) {
        const int u = t - 128;
        float a1 = 0.f, a2 = 0.f, a3 = 0.f;
#pragma unroll
        for (int e = 0; e < TE; e++) {
            const int s = sh_src[e];
            const float base = lw[e] * sh_ea[e][0];
            const float* yl = &g_l[(size_t)s * NODE_F + 64 + u * 3];
            a1 = fmaf(base, yl[0], a1);
            a2 = fmaf(base, yl[1], a2);
            a3 = fmaf(base, yl[2], a3);
            if (e == TE - 1 || sh_dst[e + 1] != sh_dst[e]) {
                float* p = &g_s[(size_t)sh_dst[e] * S_F + 256 + u * 3];
                atomicAdd(p + 0, a1);
                atomicAdd(p + 1, a2);
                atomicAdd(p + 2, a3);
                a1 = a2 = a3 = 0.f;
            }
        }
    } else {
        const int u = t - 160;
        float a0 = 0.f;
#pragma unroll
        for (int e = 0; e < TE; e++) {
            const int s = sh_src[e];
            const float* yl = &g_l[(size_t)s * NODE_F + 64 + u * 3];
            const float dotv = yl[0] * sh_ea[e][1] + yl[1] * sh_ea[e][2] +
                               yl[2] * sh_ea[e][3];
            a0 = fmaf(lw[e] * dotv, 0.5773502691896258f, a0);
            if (e == TE - 1 || sh_dst[e + 1] != sh_dst[e]) {
                atomicAdd(&g_s[(size_t)sh_dst[e] * S_F + 352 + u], a0);
                a0 = 0.f;
            }
        }
    }
}

// ---------------------------------------------------------------------------
// Node post-pass: thread-per-node, weights in smem, acc in registers.
__global__ void __launch_bounds__(256)
node_post_kernel(const float* __restrict__ attr,
                 const float* __restrict__ W00,
                 const float* __restrict__ W10,
                 const float* __restrict__ W01,
                 const float* __restrict__ W11,
                 float* __restrict__ out) {
    __shared__ float w00[4096], w10[2048], w01[2048], w11[1024];
    const int t = threadIdx.x;
    for (int i = t; i < 4096; i += 256) w00[i] = W00[i];
    for (int i = t; i < 2048; i += 256) { w10[i] = W10[i]; w01[i] = W01[i]; }
    for (int i = t; i < 1024; i += 256) w11[i] = W11[i];
    __syncthreads();

    const int n = blockIdx.x * 256 + t;
    if (n >= N_NODES) return;
    const float sc = attr[n] * 0.05103103630798288f;
    const float* sn = g_s + (size_t)n * S_F;
    float* on       = out + (size_t)n * NODE_F;

    {
        float acc[64];
#pragma unroll
        for (int i = 0; i < 64; i++) acc[i] = 0.f;
#pragma unroll 1
        for (int u4 = 0; u4 < 64; u4 += 4) {
            const float4 sv = *reinterpret_cast<const float4*>(sn + u4);
            const float xs[4] = {sv.x, sv.y, sv.z, sv.w};
#pragma unroll
            for (int j = 0; j < 4; j++) {
                const float* wrow = w00 + (u4 + j) * 64;
#pragma unroll
                for (int tt = 0; tt < 64; tt++) acc[tt] += xs[j] * wrow[tt];
            }
        }
#pragma unroll 1
        for (int u4 = 0; u4 < 32; u4 += 4) {
            const float4 sv = *reinterpret_cast<const float4*>(sn + 352 + u4);
            const float xs[4] = {sv.x, sv.y, sv.z, sv.w};
#pragma unroll
            for (int j = 0; j < 4; j++) {
                const float* wrow = w10 + (u4 + j) * 64;
#pragma unroll
                for (int tt = 0; tt < 64; tt++) acc[tt] += xs[j] * wrow[tt];
            }
        }
#pragma unroll
        for (int t4 = 0; t4 < 64; t4 += 4) {
            float4 o = *reinterpret_cast<const float4*>(on + t4);
            o.x += acc[t4] * sc;     o.y += acc[t4 + 1] * sc;
            o.z += acc[t4 + 2] * sc; o.w += acc[t4 + 3] * sc;
            *reinterpret_cast<float4*>(on + t4) = o;
        }
    }

    {
        float acc[96];
#pragma unroll
        for (int i = 0; i < 96; i++) acc[i] = 0.f;
#pragma unroll 1
        for (int u4 = 0; u4 < 64; u4 += 4) {
            const float4 v0 = *reinterpret_cast<const float4*>(sn + 64 + u4 * 3);
            const float4 v1 = *reinterpret_cast<const float4*>(sn + 64 + u4 * 3 + 4);
            const float4 v2 = *reinterpret_cast<const float4*>(sn + 64 + u4 * 3 + 8);
            const float xs[12] = {v0.x, v0.y, v0.z, v0.w, v1.x, v1.y,
                                  v1.z, v1.w, v2.x, v2.y, v2.z, v2.w};
#pragma unroll
            for (int j = 0; j < 4; j++) {
                const float* wrow = w01 + (u4 + j) * 32;
#pragma unroll
                for (int w = 0; w < 32; w++) {
                    const float wg = wrow[w];
                    acc[w * 3 + 0] += xs[j * 3 + 0] * wg;
                    acc[w * 3 + 1] += xs[j * 3 + 1] * wg;
                    acc[w * 3 + 2] += xs[j * 3 + 2] * wg;
                }
            }
        }
#pragma unroll 1
        for (int u4 = 0; u4 < 32; u4 += 4) {
            const float4 v0 = *reinterpret_cast<const float4*>(sn + 256 + u4 * 3);
            const float4 v1 = *reinterpret_cast<const float4*>(sn + 256 + u4 * 3 + 4);
            const float4 v2 = *reinterpret_cast<const float4*>(sn + 256 + u4 * 3 + 8);
            const float xs[12] = {v0.x, v0.y, v0.z, v0.w, v1.x, v1.y,
                                  v1.z, v1.w, v2.x, v2.y, v2.z, v2.w};
#pragma unroll
            for (int j = 0; j < 4; j++) {
                const float* wrow = w11 + (u4 + j) * 32;
#pragma unroll
                for (int w = 0; w < 32; w++) {
                    const float wg = wrow[w];
                    acc[w * 3 + 0] += xs[j * 3 + 0] * wg;
                    acc[w * 3 + 1] += xs[j * 3 + 1] * wg;
                    acc[w * 3 + 2] += xs[j * 3 + 2] * wg;
                }
            }
        }
#pragma unroll
        for (int i4 = 0; i4 < 96; i4 += 4) {
            float4 o = *reinterpret_cast<const float4*>(on + 64 + i4);
            o.x += acc[i4] * sc;     o.y += acc[i4 + 1] * sc;
            o.z += acc[i4 + 2] * sc; o.w += acc[i4 + 3] * sc;
            *reinterpret_cast<float4*>(on + 64 + i4) = o;
        }
    }
}

// ---------------------------------------------------------------------------
extern "C" void kernel_launch(void* const* d_in, const int* in_sizes, int n_in,
                              void* d_out, int out_size) {
    const float* node_input = (const float*)d_in[0];
    const float* node_attr  = (const float*)d_in[1];
    const float* edge_attr  = (const float*)d_in[2];
    const float* elemb      = (const float*)d_in[3];
    const float* W_si0      = (const float*)d_in[4];
    const float* W_si1      = (const float*)d_in[5];
    const float* W_l1_0     = (const float*)d_in[6];
    const float* W_l1_1     = (const float*)d_in[7];
    const float* W_l2_00    = (const float*)d_in[8];
    const float* W_l2_10    = (const float*)d_in[9];
    const float* W_l2_01    = (const float*)d_in[10];
    const float* W_l2_11    = (const float*)d_in[11];
    const float* W_fc1      = (const float*)d_in[12];
    const float* W_fc2      = (const float*)d_in[13];
    const int*   esrc       = (const int*)d_in[14];
    const int*   edst       = (const int*)d_in[15];
    float* out = (float*)d_out;

    cudaFuncSetAttribute(gemm_kernel,
                         cudaFuncAttributeMaxDynamicSharedMemorySize, SM_TOTAL);

    zero_kernel<<<2048, 256>>>();
    split_fc2_kernel<<<(NW * KROW + 255) / 256, 256>>>(W_fc2);
    hist_kernel<<<(N_EDGES + 255) / 256, 256>>>(edst);
    scan_kernel<<<1, 1024>>>();
    scatter_kernel<<<(N_EDGES + 255) / 256, 256>>>(esrc, edst);
    node_pre_kernel<<<(N_NODES + 255) / 256, 256>>>(node_input, node_attr,
                                                    W_si0, W_si1, W_l1_0,
                                                    W_l1_1, out);
    gemm_kernel<<<N_EDGES / ETG, 512, SM_TOTAL>>>(elemb, W_fc1);
    scatter_edge_kernel<<<N_EDGES / TE, 192>>>(edge_attr);
    node_post_kernel<<<(N_NODES + 255) / 256, 256>>>(node_attr, W_l2_00,
                                                     W_l2_10, W_l2_01,
                                                     W_l2_11, out);
}